// round 5
// baseline (speedup 1.0000x reference)
#include <cuda_runtime.h>
#include <cuda_fp16.h>
#include <cstdint>

#define D_    1024
#define E_    8
#define DF_   4096
#define TMAX  4096
#define BM    128
#define BN    256
#define BK    32
#define SKEW  8
#define ROWL  (BK + SKEW)              // 40 halves per smem row
#define A_STAGE (BM * ROWL)            // 5120 halves
#define B_STAGE (BN * ROWL)            // 10240 halves
#define SMEM_HALVES (2 * A_STAGE + 2 * B_STAGE)
#define SMEM_BYTES  (SMEM_HALVES * 2)  // 61440

// ---------------- scratch (device globals; no runtime allocation) ----------
__device__ int    g_cnt[E_];
__device__ int    g_off[E_];
__device__ int    g_tok[E_ * TMAX];
__device__ float  g_w  [E_ * TMAX];
__device__ __half g_xh [(size_t)TMAX * D_];                  // LN output, fp16 (8MB)
__device__ __half g_h  [(size_t)2 * TMAX * DF_];             // expert hidden, compact (64MB)

// ---------------- mma helpers ---------------------------------------------
__device__ __forceinline__ uint32_t smem_u32(const void* p) {
    return (uint32_t)__cvta_generic_to_shared(p);
}
__device__ __forceinline__ void ldm_x4(uint32_t* r, uint32_t a) {
    asm volatile("ldmatrix.sync.aligned.m8n8.x4.shared.b16 {%0,%1,%2,%3}, [%4];\n"
                 : "=r"(r[0]), "=r"(r[1]), "=r"(r[2]), "=r"(r[3]) : "r"(a));
}
__device__ __forceinline__ void mma16816(float* c, const uint32_t* a, const uint32_t* b) {
    asm volatile(
        "mma.sync.aligned.m16n8k16.row.col.f32.f16.f16.f32 "
        "{%0,%1,%2,%3}, {%4,%5,%6,%7}, {%8,%9}, {%0,%1,%2,%3};\n"
        : "+f"(c[0]), "+f"(c[1]), "+f"(c[2]), "+f"(c[3])
        : "r"(a[0]), "r"(a[1]), "r"(a[2]), "r"(a[3]), "r"(b[0]), "r"(b[1]));
}
__device__ __forceinline__ uint32_t h2u(__half2 v) {
    return *reinterpret_cast<uint32_t*>(&v);
}
__device__ __forceinline__ float gelu_exact(float v) {
    return 0.5f * v * (1.0f + erff(v * 0.70710678118654752440f));
}

// ---------------- kernel 0: reset dispatch counters -----------------------
__global__ void reset_kernel() {
    if (threadIdx.x < E_) g_cnt[threadIdx.x] = 0;
}
// ---------------- kernel 0b: exclusive prefix sum of counts ---------------
__global__ void offsets_kernel() {
    if (threadIdx.x == 0) {
        int o = 0;
#pragma unroll
        for (int e = 0; e < E_; ++e) { g_off[e] = o; o += g_cnt[e]; }
    }
}

// ---------------- kernel 1: LayerNorm + router + dispatch -----------------
__global__ __launch_bounds__(256) void ln_gate_kernel(
    const float* __restrict__ x, const float* __restrict__ gamma,
    const float* __restrict__ beta, const float* __restrict__ Wg,
    const float* __restrict__ bg, float* __restrict__ out) {
    const int t   = blockIdx.x;
    const int tid = threadIdx.x;
    const int lane = tid & 31, warp = tid >> 5;

    __shared__ float red[2][8];
    __shared__ float ared[E_][8];
    __shared__ float logits[E_];

    const float4 v = reinterpret_cast<const float4*>(x + (size_t)t * D_)[tid];
    float s  = v.x + v.y + v.z + v.w;
    float ss = v.x * v.x + v.y * v.y + v.z * v.z + v.w * v.w;
#pragma unroll
    for (int o = 16; o > 0; o >>= 1) {
        s  += __shfl_down_sync(0xffffffffu, s, o);
        ss += __shfl_down_sync(0xffffffffu, ss, o);
    }
    if (lane == 0) { red[0][warp] = s; red[1][warp] = ss; }
    __syncthreads();
    if (warp == 0) {
        float a = (lane < 8) ? red[0][lane] : 0.f;
        float b = (lane < 8) ? red[1][lane] : 0.f;
#pragma unroll
        for (int o = 4; o > 0; o >>= 1) {
            a += __shfl_down_sync(0xffffffffu, a, o);
            b += __shfl_down_sync(0xffffffffu, b, o);
        }
        if (lane == 0) { red[0][0] = a; red[1][0] = b; }
    }
    __syncthreads();
    const float mu   = red[0][0] * (1.0f / D_);
    const float var  = red[1][0] * (1.0f / D_) - mu * mu;
    const float rstd = rsqrtf(var + 1e-5f);

    const float4 g  = reinterpret_cast<const float4*>(gamma)[tid];
    const float4 be = reinterpret_cast<const float4*>(beta)[tid];
    const float xn0 = (v.x - mu) * rstd * g.x + be.x;
    const float xn1 = (v.y - mu) * rstd * g.y + be.y;
    const float xn2 = (v.z - mu) * rstd * g.z + be.z;
    const float xn3 = (v.w - mu) * rstd * g.w + be.w;

    // residual init: out = x (expert contributions atomically added later)
    reinterpret_cast<float4*>(out + (size_t)t * D_)[tid] = v;
    __half2* xh2 = reinterpret_cast<__half2*>(g_xh + (size_t)t * D_);
    xh2[tid * 2 + 0] = __floats2half2_rn(xn0, xn1);
    xh2[tid * 2 + 1] = __floats2half2_rn(xn2, xn3);

    float acc[E_];
#pragma unroll
    for (int e = 0; e < E_; ++e) {
        const float4 w = reinterpret_cast<const float4*>(Wg + (size_t)e * D_)[tid];
        acc[e] = xn0 * w.x + xn1 * w.y + xn2 * w.z + xn3 * w.w;
    }
#pragma unroll
    for (int e = 0; e < E_; ++e) {
        float a = acc[e];
#pragma unroll
        for (int o = 16; o > 0; o >>= 1) a += __shfl_down_sync(0xffffffffu, a, o);
        if (lane == 0) ared[e][warp] = a;
    }
    __syncthreads();
    if (tid < E_) {
        float a = 0.f;
#pragma unroll
        for (int w = 0; w < 8; ++w) a += ared[tid][w];
        logits[tid] = a + bg[tid];
    }
    __syncthreads();
    if (tid == 0) {
        float m = logits[0];
#pragma unroll
        for (int e = 1; e < E_; ++e) m = fmaxf(m, logits[e]);
        float p[E_], Z = 0.f;
#pragma unroll
        for (int e = 0; e < E_; ++e) { p[e] = expf(logits[e] - m); Z += p[e]; }
        int i1 = 0;
#pragma unroll
        for (int e = 1; e < E_; ++e) if (p[e] > p[i1]) i1 = e;
        int i2 = (i1 == 0) ? 1 : 0;
#pragma unroll
        for (int e = 0; e < E_; ++e) if (e != i1 && p[e] > p[i2]) i2 = e;
        const float p1 = p[i1] / Z, p2 = p[i2] / Z;
        const float dn = p1 + p2 + 1e-8f;
        int pos1 = atomicAdd(&g_cnt[i1], 1);
        g_tok[i1 * TMAX + pos1] = t; g_w[i1 * TMAX + pos1] = p1 / dn;
        int pos2 = atomicAdd(&g_cnt[i2], 1);
        g_tok[i2 * TMAX + pos2] = t; g_w[i2 * TMAX + pos2] = p2 / dn;
    }
}

// ---------------- GEMM: MODE 0 = gemm1(H=gelu), MODE 1 = gemm2(scatter) ----
// CTA tile 128x256xBK32, 8 warps 2x4, warp tile 64x64. Double-buffered smem.
template <int KLEN, int MODE>
__global__ __launch_bounds__(256, 1) void moe_gemm_kernel(
    const float* __restrict__ Wt, const float* __restrict__ bias,
    float* __restrict__ out) {
    const int e  = blockIdx.z;
    const int M  = g_cnt[e];
    const int m0 = blockIdx.x * BM;
    if (m0 >= M) return;
    const int n0 = blockIdx.y * BN;
    const int hb = g_off[e];

    extern __shared__ __half sm[];
    __half* As = sm;                       // [2][BM][ROWL]
    __half* Bs = sm + 2 * A_STAGE;         // [2][BN][ROWL]

    const int tid  = threadIdx.x;
    const int lane = tid & 31, wid = tid >> 5;
    const int warp_m = wid >> 2, warp_n = wid & 3;   // 2 x 4

    // ---- A loader: 2 threads/row, 16 halves each ----
    const int ar   = tid >> 1;
    const int ac   = (tid & 1) * 16;
    const int rgc  = (m0 + ar < M) ? (m0 + ar) : (M - 1);       // clamped global row
    const __half* arow = (MODE == 0)
        ? g_xh + (size_t)g_tok[e * TMAX + rgc] * D_
        : g_h  + (size_t)(hb + rgc) * (size_t)DF_;
    // ---- B loader: 1 thread/row, 32 floats each ----
    const float* brow = (MODE == 0)
        ? Wt + ((size_t)e * DF_ + n0 + tid) * (size_t)D_
        : Wt + ((size_t)e * D_  + n0 + tid) * (size_t)DF_;

    uint4  aR[2];
    float4 bR[8];
    auto ldregs = [&](int k0) {
        const uint4* ap = (const uint4*)(arow + k0 + ac);
        aR[0] = ap[0]; aR[1] = ap[1];
        const float4* bp = (const float4*)(brow + k0);
#pragma unroll
        for (int i = 0; i < 8; ++i) bR[i] = bp[i];
    };
    auto sts = [&](int buf) {
        __half* Ad = As + buf * A_STAGE + ar * ROWL + ac;
        *(uint4*)(Ad)     = aR[0];
        *(uint4*)(Ad + 8) = aR[1];
        __half* Bd = Bs + buf * B_STAGE + tid * ROWL;
#pragma unroll
        for (int i = 0; i < 4; ++i) {
            uint4 h;
            h.x = h2u(__floats2half2_rn(bR[2 * i].x,     bR[2 * i].y));
            h.y = h2u(__floats2half2_rn(bR[2 * i].z,     bR[2 * i].w));
            h.z = h2u(__floats2half2_rn(bR[2 * i + 1].x, bR[2 * i + 1].y));
            h.w = h2u(__floats2half2_rn(bR[2 * i + 1].z, bR[2 * i + 1].w));
            *(uint4*)(Bd + i * 8) = h;
        }
    };

    float acc[4][8][4];
#pragma unroll
    for (int i = 0; i < 4; ++i)
#pragma unroll
        for (int j = 0; j < 8; ++j)
#pragma unroll
            for (int k = 0; k < 4; ++k) acc[i][j][k] = 0.f;

    ldregs(0);
    sts(0);
    __syncthreads();

    const int NKT = KLEN / BK;
    for (int kt = 0; kt < NKT; ++kt) {
        const int buf = kt & 1;
        const bool more = (kt + 1 < NKT);
        if (more) ldregs((kt + 1) * BK);     // LDG overlaps compute below

        const __half* Ab = As + buf * A_STAGE;
        const __half* Bb = Bs + buf * B_STAGE;
#pragma unroll
        for (int ks = 0; ks < 2; ++ks) {
            const int kc = ks * 16;
            uint32_t af[4][4];
            uint32_t bf[8][2];
#pragma unroll
            for (int mt = 0; mt < 4; ++mt) {
                uint32_t ad = smem_u32(
                    Ab + (warp_m * 64 + mt * 16 + (lane & 15)) * ROWL
                       + kc + (lane >> 4) * 8);
                ldm_x4(af[mt], ad);
            }
#pragma unroll
            for (int np = 0; np < 4; ++np) {   // pairs of n-tiles via x4
                uint32_t bd = smem_u32(
                    Bb + (warp_n * 64 + np * 16 + ((lane >> 4) & 1) * 8 + (lane & 7)) * ROWL
                       + kc + ((lane >> 3) & 1) * 8);
                uint32_t r4[4];
                ldm_x4(r4, bd);
                bf[2 * np][0]     = r4[0]; bf[2 * np][1]     = r4[1];
                bf[2 * np + 1][0] = r4[2]; bf[2 * np + 1][1] = r4[3];
            }
#pragma unroll
            for (int mt = 0; mt < 4; ++mt)
#pragma unroll
                for (int nt = 0; nt < 8; ++nt)
                    mma16816(acc[mt][nt], af[mt], bf[nt]);
        }

        if (more) sts(buf ^ 1);              // write other buffer; no race
        __syncthreads();
    }

    // ---- epilogue ----
    const int gr = lane >> 2;
    const int gc = (lane & 3) * 2;
#pragma unroll
    for (int mt = 0; mt < 4; ++mt) {
#pragma unroll
        for (int h = 0; h < 2; ++h) {
            const int r = warp_m * 64 + mt * 16 + gr + h * 8;
            if (m0 + r < M) {
                if (MODE == 0) {
                    const size_t rowbase = (size_t)(hb + m0 + r) * DF_ + n0;
                    const float* bb = bias + (size_t)e * DF_ + n0;
#pragma unroll
                    for (int nt = 0; nt < 8; ++nt) {
                        const int col = warp_n * 64 + nt * 8 + gc;
                        float v0 = acc[mt][nt][h * 2 + 0] + __ldg(bb + col);
                        float v1 = acc[mt][nt][h * 2 + 1] + __ldg(bb + col + 1);
                        v0 = gelu_exact(v0);
                        v1 = gelu_exact(v1);
                        *(__half2*)&g_h[rowbase + col] = __floats2half2_rn(v0, v1);
                    }
                } else {
                    const int   tok = g_tok[e * TMAX + m0 + r];
                    const float wgt = g_w[e * TMAX + m0 + r];
                    float* orow = out + (size_t)tok * D_ + n0;
                    const float* bb = bias + (size_t)e * D_ + n0;
#pragma unroll
                    for (int nt = 0; nt < 8; ++nt) {
                        const int col = warp_n * 64 + nt * 8 + gc;
                        const float v0 = acc[mt][nt][h * 2 + 0] + __ldg(bb + col);
                        const float v1 = acc[mt][nt][h * 2 + 1] + __ldg(bb + col + 1);
                        atomicAdd(orow + col,     wgt * v0);
                        atomicAdd(orow + col + 1, wgt * v1);
                    }
                }
            }
        }
    }
}

// ---------------- launch ----------------------------------------------------
extern "C" void kernel_launch(void* const* d_in, const int* in_sizes, int n_in,
                              void* d_out, int out_size) {
    const float* x     = (const float*)d_in[0];
    const float* gamma = (const float*)d_in[1];
    const float* beta  = (const float*)d_in[2];
    const float* Wg    = (const float*)d_in[3];
    const float* bg    = (const float*)d_in[4];
    const float* W1    = (const float*)d_in[5];
    const float* b1    = (const float*)d_in[6];
    const float* W2    = (const float*)d_in[7];
    const float* b2    = (const float*)d_in[8];
    float* out = (float*)d_out;

    const int T  = in_sizes[0] / D_;              // 4096
    const int mt = (T + BM - 1) / BM;             // 32

    // idempotent + deterministic; safe under graph capture (host-side API)
    cudaFuncSetAttribute(moe_gemm_kernel<D_, 0>,
                         cudaFuncAttributeMaxDynamicSharedMemorySize, SMEM_BYTES);
    cudaFuncSetAttribute(moe_gemm_kernel<DF_, 1>,
                         cudaFuncAttributeMaxDynamicSharedMemorySize, SMEM_BYTES);

    reset_kernel<<<1, 32>>>();
    ln_gate_kernel<<<T, 256>>>(x, gamma, beta, Wg, bg, out);
    offsets_kernel<<<1, 32>>>();
    dim3 g1(mt, DF_ / BN, E_);                    // m fastest -> W1 L2 reuse
    moe_gemm_kernel<D_, 0><<<g1, 256, SMEM_BYTES>>>(W1, b1, nullptr);
    dim3 g2(mt, D_ / BN, E_);
    moe_gemm_kernel<DF_, 1><<<g2, 256, SMEM_BYTES>>>(W2, b2, out);
}

// round 6
// speedup vs baseline: 1.7282x; 1.7282x over previous
#include <cuda_runtime.h>
#include <cuda_fp16.h>
#include <cstdint>

#define D_    1024
#define E_    8
#define DF_   4096
#define TMAX  4096
#define BM    128
#define BN    128
#define BK    32
#define SKEW  8
#define ROWL  (BK + SKEW)                 // 40 halves = 80B rows (16B aligned)
#define STAGES 4
#define A_STAGE (BM * ROWL)               // 5120 halves per stage (A==B size)
#define SMEM_BYTES (STAGES * 2 * A_STAGE * 2)   // 81920 B

// ---------------- scratch (device globals; no runtime allocation) ----------
__device__ int    g_cnt[E_];
__device__ int    g_off[E_];
__device__ int    g_tok[E_ * TMAX];
__device__ float  g_w  [E_ * TMAX];
__device__ __half g_xh [(size_t)TMAX * D_];            // LN output fp16 (8MB)
__device__ __half g_h  [(size_t)2 * TMAX * DF_];       // hidden, compact (64MB)
__device__ __half g_w1h[(size_t)E_ * DF_ * D_];        // W1 fp16 (64MB)
__device__ __half g_w2h[(size_t)E_ * D_ * DF_];        // W2 fp16 (64MB)

// ---------------- helpers ---------------------------------------------------
__device__ __forceinline__ uint32_t smem_u32(const void* p) {
    return (uint32_t)__cvta_generic_to_shared(p);
}
__device__ __forceinline__ void ldm_x4(uint32_t* r, uint32_t a) {
    asm volatile("ldmatrix.sync.aligned.m8n8.x4.shared.b16 {%0,%1,%2,%3}, [%4];\n"
                 : "=r"(r[0]), "=r"(r[1]), "=r"(r[2]), "=r"(r[3]) : "r"(a));
}
__device__ __forceinline__ void mma16816(float* c, const uint32_t* a, const uint32_t* b) {
    asm volatile(
        "mma.sync.aligned.m16n8k16.row.col.f32.f16.f16.f32 "
        "{%0,%1,%2,%3}, {%4,%5,%6,%7}, {%8,%9}, {%0,%1,%2,%3};\n"
        : "+f"(c[0]), "+f"(c[1]), "+f"(c[2]), "+f"(c[3])
        : "r"(a[0]), "r"(a[1]), "r"(a[2]), "r"(a[3]), "r"(b[0]), "r"(b[1]));
}
__device__ __forceinline__ void cp16(uint32_t dst, const void* src) {
    asm volatile("cp.async.cg.shared.global [%0], [%1], 16;\n"
                 :: "r"(dst), "l"(src));
}
#define CP_COMMIT() asm volatile("cp.async.commit_group;\n" ::: "memory")
#define CP_WAIT2()  asm volatile("cp.async.wait_group 2;\n" ::: "memory")
__device__ __forceinline__ uint32_t h2u(__half2 v) {
    return *reinterpret_cast<uint32_t*>(&v);
}
__device__ __forceinline__ float gelu_exact(float v) {
    return 0.5f * v * (1.0f + erff(v * 0.70710678118654752440f));
}

// ---------------- kernel 0: reset dispatch counters ------------------------
__global__ void reset_kernel() {
    if (threadIdx.x < E_) g_cnt[threadIdx.x] = 0;
}
// ---------------- kernel 0b: exclusive prefix sum ---------------------------
__global__ void offsets_kernel() {
    if (threadIdx.x == 0) {
        int o = 0;
#pragma unroll
        for (int e = 0; e < E_; ++e) { g_off[e] = o; o += g_cnt[e]; }
    }
}
// ---------------- kernel 0c: weights fp32 -> fp16 ---------------------------
__global__ __launch_bounds__(256) void convert_w_kernel(
    const float* __restrict__ W1, const float* __restrict__ W2) {
    const size_t n = (size_t)E_ * DF_ * D_ / 4;       // float4 count per tensor
    for (size_t i = (size_t)blockIdx.x * blockDim.x + threadIdx.x; i < 2 * n;
         i += (size_t)gridDim.x * blockDim.x) {
        float4 v; uint2* dst;
        if (i < n) { v = ((const float4*)W1)[i]; dst = (uint2*)g_w1h + i; }
        else       { v = ((const float4*)W2)[i - n]; dst = (uint2*)g_w2h + (i - n); }
        uint2 u;
        u.x = h2u(__floats2half2_rn(v.x, v.y));
        u.y = h2u(__floats2half2_rn(v.z, v.w));
        *dst = u;
    }
}

// ---------------- kernel 1: LayerNorm + router + dispatch -------------------
__global__ __launch_bounds__(256) void ln_gate_kernel(
    const float* __restrict__ x, const float* __restrict__ gamma,
    const float* __restrict__ beta, const float* __restrict__ Wg,
    const float* __restrict__ bg, float* __restrict__ out) {
    const int t   = blockIdx.x;
    const int tid = threadIdx.x;
    const int lane = tid & 31, warp = tid >> 5;

    __shared__ float red[2][8];
    __shared__ float ared[E_][8];
    __shared__ float logits[E_];

    const float4 v = reinterpret_cast<const float4*>(x + (size_t)t * D_)[tid];
    float s  = v.x + v.y + v.z + v.w;
    float ss = v.x * v.x + v.y * v.y + v.z * v.z + v.w * v.w;
#pragma unroll
    for (int o = 16; o > 0; o >>= 1) {
        s  += __shfl_down_sync(0xffffffffu, s, o);
        ss += __shfl_down_sync(0xffffffffu, ss, o);
    }
    if (lane == 0) { red[0][warp] = s; red[1][warp] = ss; }
    __syncthreads();
    if (warp == 0) {
        float a = (lane < 8) ? red[0][lane] : 0.f;
        float b = (lane < 8) ? red[1][lane] : 0.f;
#pragma unroll
        for (int o = 4; o > 0; o >>= 1) {
            a += __shfl_down_sync(0xffffffffu, a, o);
            b += __shfl_down_sync(0xffffffffu, b, o);
        }
        if (lane == 0) { red[0][0] = a; red[1][0] = b; }
    }
    __syncthreads();
    const float mu   = red[0][0] * (1.0f / D_);
    const float var  = red[1][0] * (1.0f / D_) - mu * mu;
    const float rstd = rsqrtf(var + 1e-5f);

    const float4 g  = reinterpret_cast<const float4*>(gamma)[tid];
    const float4 be = reinterpret_cast<const float4*>(beta)[tid];
    const float xn0 = (v.x - mu) * rstd * g.x + be.x;
    const float xn1 = (v.y - mu) * rstd * g.y + be.y;
    const float xn2 = (v.z - mu) * rstd * g.z + be.z;
    const float xn3 = (v.w - mu) * rstd * g.w + be.w;

    // residual init: out = x
    reinterpret_cast<float4*>(out + (size_t)t * D_)[tid] = v;
    __half2* xh2 = reinterpret_cast<__half2*>(g_xh + (size_t)t * D_);
    xh2[tid * 2 + 0] = __floats2half2_rn(xn0, xn1);
    xh2[tid * 2 + 1] = __floats2half2_rn(xn2, xn3);

    float acc[E_];
#pragma unroll
    for (int e = 0; e < E_; ++e) {
        const float4 w = reinterpret_cast<const float4*>(Wg + (size_t)e * D_)[tid];
        acc[e] = xn0 * w.x + xn1 * w.y + xn2 * w.z + xn3 * w.w;
    }
#pragma unroll
    for (int e = 0; e < E_; ++e) {
        float a = acc[e];
#pragma unroll
        for (int o = 16; o > 0; o >>= 1) a += __shfl_down_sync(0xffffffffu, a, o);
        if (lane == 0) ared[e][warp] = a;
    }
    __syncthreads();
    if (tid < E_) {
        float a = 0.f;
#pragma unroll
        for (int w = 0; w < 8; ++w) a += ared[tid][w];
        logits[tid] = a + bg[tid];
    }
    __syncthreads();
    if (tid == 0) {
        float m = logits[0];
#pragma unroll
        for (int e = 1; e < E_; ++e) m = fmaxf(m, logits[e]);
        float p[E_], Z = 0.f;
#pragma unroll
        for (int e = 0; e < E_; ++e) { p[e] = expf(logits[e] - m); Z += p[e]; }
        int i1 = 0;
#pragma unroll
        for (int e = 1; e < E_; ++e) if (p[e] > p[i1]) i1 = e;
        int i2 = (i1 == 0) ? 1 : 0;
#pragma unroll
        for (int e = 0; e < E_; ++e) if (e != i1 && p[e] > p[i2]) i2 = e;
        const float p1 = p[i1] / Z, p2 = p[i2] / Z;
        const float dn = p1 + p2 + 1e-8f;
        int pos1 = atomicAdd(&g_cnt[i1], 1);
        g_tok[i1 * TMAX + pos1] = t; g_w[i1 * TMAX + pos1] = p1 / dn;
        int pos2 = atomicAdd(&g_cnt[i2], 1);
        g_tok[i2 * TMAX + pos2] = t; g_w[i2 * TMAX + pos2] = p2 / dn;
    }
}

// ---------------- GEMM: 128x128x32, 8 warps 2x4 (warp 64x32),
//                  4-stage cp.async pipeline, fp16 weights ------------------
template <int KLEN, int MODE>
__global__ __launch_bounds__(256, 2) void moe_gemm_kernel(
    const float* __restrict__ bias, float* __restrict__ out) {
    const int e  = blockIdx.z;
    const int M  = g_cnt[e];
    const int m0 = blockIdx.x * BM;
    if (m0 >= M) return;
    const int n0 = blockIdx.y * BN;
    const int hb = g_off[e];

    extern __shared__ __half sm[];
    __half* As = sm;                          // [STAGES][BM][ROWL]
    __half* Bs = sm + STAGES * A_STAGE;       // [STAGES][BN][ROWL]

    const int tid  = threadIdx.x;
    const int lane = tid & 31, wid = tid >> 5;
    const int warp_m = wid >> 2, warp_n = wid & 3;    // 2 x 4

    // loaders: 2 threads/row, 32B (2x16B cp.async) each, for both A and B
    const int ar  = tid >> 1;
    const int ac  = (tid & 1) * 16;
    const int rgc = (m0 + ar < M) ? (m0 + ar) : (M - 1);   // clamped row
    const __half* arow = (MODE == 0)
        ? g_xh + (size_t)g_tok[e * TMAX + rgc] * D_ + ac
        : g_h  + (size_t)(hb + rgc) * (size_t)DF_ + ac;
    const __half* brow = (MODE == 0)
        ? g_w1h + ((size_t)e * DF_ + n0 + ar) * (size_t)D_ + ac
        : g_w2h + ((size_t)e * D_  + n0 + ar) * (size_t)DF_ + ac;
    const uint32_t adst = smem_u32(As + ar * ROWL + ac);
    const uint32_t bdst = smem_u32(Bs + ar * ROWL + ac);

    auto load_stage = [&](int kt, int buf) {
        const uint32_t so = buf * (A_STAGE * 2);     // byte offset per stage
        const __half* as = arow + kt * BK;
        cp16(adst + so,      as);
        cp16(adst + so + 16, as + 8);
        const __half* bs = brow + kt * BK;
        cp16(bdst + so,      bs);
        cp16(bdst + so + 16, bs + 8);
    };

    float acc[4][4][4];
#pragma unroll
    for (int i = 0; i < 4; ++i)
#pragma unroll
        for (int j = 0; j < 4; ++j)
#pragma unroll
            for (int k = 0; k < 4; ++k) acc[i][j][k] = 0.f;

    // prologue: stages 0..2 in flight
#pragma unroll
    for (int s = 0; s < STAGES - 1; ++s) { load_stage(s, s); CP_COMMIT(); }

    const int NKT = KLEN / BK;
    for (int kt = 0; kt < NKT; ++kt) {
        CP_WAIT2();                 // stage kt landed
        __syncthreads();            // all warps done reading buffer (kt-1)&3
        if (kt + STAGES - 1 < NKT) load_stage(kt + STAGES - 1, (kt + STAGES - 1) & 3);
        CP_COMMIT();                // commit (possibly empty) to keep group count

        const __half* Ab = As + (kt & 3) * A_STAGE;
        const __half* Bb = Bs + (kt & 3) * A_STAGE;
#pragma unroll
        for (int ks = 0; ks < 2; ++ks) {
            const int kc = ks * 16;
            uint32_t af[4][4];
            uint32_t bf[4][2];
#pragma unroll
            for (int mt = 0; mt < 4; ++mt) {
                uint32_t ad = smem_u32(
                    Ab + (warp_m * 64 + mt * 16 + (lane & 15)) * ROWL
                       + kc + (lane >> 4) * 8);
                ldm_x4(af[mt], ad);
            }
#pragma unroll
            for (int np = 0; np < 2; ++np) {
                uint32_t bd = smem_u32(
                    Bb + (warp_n * 32 + np * 16 + ((lane >> 4) & 1) * 8 + (lane & 7)) * ROWL
                       + kc + ((lane >> 3) & 1) * 8);
                uint32_t r4[4];
                ldm_x4(r4, bd);
                bf[2 * np][0]     = r4[0]; bf[2 * np][1]     = r4[1];
                bf[2 * np + 1][0] = r4[2]; bf[2 * np + 1][1] = r4[3];
            }
#pragma unroll
            for (int mt = 0; mt < 4; ++mt)
#pragma unroll
                for (int nt = 0; nt < 4; ++nt)
                    mma16816(acc[mt][nt], af[mt], bf[nt]);
        }
    }

    // ---- epilogue ----
    const int gr = lane >> 2;
    const int gc = (lane & 3) * 2;
#pragma unroll
    for (int mt = 0; mt < 4; ++mt) {
#pragma unroll
        for (int h = 0; h < 2; ++h) {
            const int r = warp_m * 64 + mt * 16 + gr + h * 8;
            if (m0 + r < M) {
                if (MODE == 0) {
                    const size_t rowbase = (size_t)(hb + m0 + r) * DF_ + n0;
                    const float* bb = bias + (size_t)e * DF_ + n0;
#pragma unroll
                    for (int nt = 0; nt < 4; ++nt) {
                        const int col = warp_n * 32 + nt * 8 + gc;
                        float v0 = acc[mt][nt][h * 2 + 0] + __ldg(bb + col);
                        float v1 = acc[mt][nt][h * 2 + 1] + __ldg(bb + col + 1);
                        v0 = gelu_exact(v0);
                        v1 = gelu_exact(v1);
                        *(__half2*)&g_h[rowbase + col] = __floats2half2_rn(v0, v1);
                    }
                } else {
                    const int   tok = g_tok[e * TMAX + m0 + r];
                    const float wgt = g_w[e * TMAX + m0 + r];
                    float* orow = out + (size_t)tok * D_ + n0;
                    const float* bb = bias + (size_t)e * D_ + n0;
#pragma unroll
                    for (int nt = 0; nt < 4; ++nt) {
                        const int col = warp_n * 32 + nt * 8 + gc;
                        const float v0 = acc[mt][nt][h * 2 + 0] + __ldg(bb + col);
                        const float v1 = acc[mt][nt][h * 2 + 1] + __ldg(bb + col + 1);
                        atomicAdd(orow + col,     wgt * v0);
                        atomicAdd(orow + col + 1, wgt * v1);
                    }
                }
            }
        }
    }
}

// ---------------- launch ----------------------------------------------------
extern "C" void kernel_launch(void* const* d_in, const int* in_sizes, int n_in,
                              void* d_out, int out_size) {
    const float* x     = (const float*)d_in[0];
    const float* gamma = (const float*)d_in[1];
    const float* beta  = (const float*)d_in[2];
    const float* Wg    = (const float*)d_in[3];
    const float* bg    = (const float*)d_in[4];
    const float* W1    = (const float*)d_in[5];
    const float* b1    = (const float*)d_in[6];
    const float* W2    = (const float*)d_in[7];
    const float* b2    = (const float*)d_in[8];
    float* out = (float*)d_out;

    const int T  = in_sizes[0] / D_;              // 4096
    const int mt = (T + BM - 1) / BM;             // 32

    cudaFuncSetAttribute(moe_gemm_kernel<D_, 0>,
                         cudaFuncAttributeMaxDynamicSharedMemorySize, SMEM_BYTES);
    cudaFuncSetAttribute(moe_gemm_kernel<DF_, 1>,
                         cudaFuncAttributeMaxDynamicSharedMemorySize, SMEM_BYTES);

    reset_kernel<<<1, 32>>>();
    convert_w_kernel<<<4096, 256>>>(W1, W2);
    ln_gate_kernel<<<T, 256>>>(x, gamma, beta, Wg, bg, out);
    offsets_kernel<<<1, 32>>>();
    dim3 g1(mt, DF_ / BN, E_);                    // m fastest -> W1 L2 reuse
    moe_gemm_kernel<D_, 0><<<g1, 256, SMEM_BYTES>>>(b1, nullptr);
    dim3 g2(mt, D_ / BN, E_);
    moe_gemm_kernel<DF_, 1><<<g2, 256, SMEM_BYTES>>>(b2, out);
}